// round 9
// baseline (speedup 1.0000x reference)
#include <cuda_runtime.h>
#include <cuda_fp16.h>
#include <cstdint>

#define Hh 64
#define Ww 64
#define Cc 128
#define Dd 256
#define KTOT 1152
#define NCH 36              // K chunks of 32
#define STG_SZ 1360         // staged x tile: 5 ch x 4 rows x 68 cols (halves)
#define PBS 136             // packed-B row stride (u32), conflict-free

// Pre-permuted fp16 weights in m16n8k16 fragment order:
// u32 index: [chunk][dblk][ks2(2)][warp_m(2)][mt(4)][lane(32)][slot(4)], half = +par
__device__ __half g_A[NCH * 2 * 4096];

static __device__ __forceinline__ uint32_t prmt5410(uint32_t lo, uint32_t hi) {
    uint32_t r;
    asm("prmt.b32 %0, %1, %2, 0x5410;" : "=r"(r) : "r"(lo), "r"(hi));
    return r;
}

// ---------------------------------------------------------------------------
// Build A in m16n8k16 fragment order. W[d][k], k = c*9 + kh*3 + kw.
// ---------------------------------------------------------------------------
__global__ void build_A_kernel(const float* __restrict__ c0,
                               const float* __restrict__ c1,
                               const float* __restrict__ c2) {
    int d = blockIdx.x, t = threadIdx.x;
    __shared__ float sA[72];
    if (t < 72) {
        int r = t / 9, k = t % 9, kh = k / 3, kw = k % 3;
        float a = 0.f;
        #pragma unroll
        for (int s = 0; s < 4; s++)
            a += c1[d * 96 + r * 12 + kh * 4 + s] * c2[d * 12 + s * 3 + kw];
        sA[t] = a;
    }
    __syncthreads();
    int c = t;
    float cr[8];
    #pragma unroll
    for (int r = 0; r < 8; r++) cr[r] = c0[d * 1024 + c * 8 + r];

    const int dblk = d >> 7, ml = d & 127;
    const int mhalf = ml >> 6, mt = (ml >> 4) & 3, mm = ml & 15;
    const int g = mm & 7, hi = mm >> 3;

    #pragma unroll
    for (int tap = 0; tap < 9; tap++) {
        float w = 0.f;
        #pragma unroll
        for (int r = 0; r < 8; r++) w += cr[r] * sA[r * 9 + tap];
        int k = c * 9 + tap;
        int chunk = k >> 5, kr = k & 31;
        int ks2 = kr >> 4, kk = kr & 15;
        int tig = (kk >> 1) & 3, par = kk & 1, khi = kk >> 3;
        int lane = g * 4 + tig, slot = khi * 2 + hi;
        size_t u32i = (size_t)(chunk * 2 + dblk) * 2048 +
                      (((ks2 * 2 + mhalf) * 4 + mt) * 128 + lane * 4 + slot);
        g_A[u32i * 2 + par] = __float2half_rn(w);
    }
}

// ---------------------------------------------------------------------------
// Main: im2col GEMM-conv, mma.sync m16n8k16 f16 (f32 acc). K-chunk 32.
// Grid (2 dblk, 32 row-pairs, 32 imgs). 256 thr = 8 warps (2 M x 4 N).
// Packed-B smem tile; A fragments direct from gmem (L1/L2 shared).
// ---------------------------------------------------------------------------
__global__ void __launch_bounds__(256, 2)
conv_main(const float* __restrict__ x, const float* __restrict__ bias,
          float* __restrict__ out) {
    __shared__ __half stg[2][STG_SZ];           // staged x tile (fp16)
    __shared__ uint32_t pB[2][16 * PBS];        // packed B (k-pair halves)
    __shared__ unsigned short offt[KTOT];       // im2col offset table

    const int tid = threadIdx.x;
    const int wid = tid >> 5, lid = tid & 31;
    const int g = lid >> 2, tig = lid & 3;
    const int warp_m = wid & 1, warp_n = wid >> 1;
    const int dblk = blockIdx.x;
    const int y0 = blockIdx.y * 2;
    const int img = blockIdx.z;
    const float* xim = x + (size_t)img * Cc * Hh * Ww;

    // ---- build offset table (once) ----
    for (int k = tid; k < KTOT; k += 256) {
        int chunk = k >> 5;
        int c = k / 9, tap = k - c * 9;
        int c_lo = (chunk * 32) / 9;
        int kh = tap / 3, kw = tap - kh * 3;
        offt[k] = (unsigned short)((c - c_lo) * 272 + kh * 68 + kw);
    }

    float acc[4][4][4];
    #pragma unroll
    for (int mt = 0; mt < 4; mt++)
        #pragma unroll
        for (int nt = 0; nt < 4; nt++)
            #pragma unroll
            for (int i = 0; i < 4; i++) acc[mt][nt][i] = 0.f;

    __half st[6];

    // ---- x-tile LDGs for `chunk` into regs (fp16 rounding at stage) ----
    auto ldst = [&](int chunk) {
        int c_lo = (chunk * 32) / 9;
        #pragma unroll
        for (int i = 0; i < 6; i++) {
            int e = tid + i * 256;
            float v = 0.f;
            if (e < STG_SZ) {
                int cc = e / 272, rem = e - cc * 272;
                int rr = rem / 68, col = rem - rr * 68;
                int c = c_lo + cc, gy = y0 - 1 + rr, gx = col - 1;
                if (c < Cc && (unsigned)gy < Hh && (unsigned)gx < Ww)
                    v = xim[((size_t)c << 12) + (gy << 6) + gx];
            }
            st[i] = __float2half_rn(v);
        }
    };
    auto stst = [&](int buf) {
        #pragma unroll
        for (int i = 0; i < 6; i++) {
            int e = tid + i * 256;
            if (e < STG_SZ) stg[buf][e] = st[i];
        }
    };

    // ---- build packed-B tile: pent(kp,n) = (x[2kp], x[2kp+1]) fp16 pair ----
    auto build = [&](int chunk, int buf) {
        const unsigned short* stp = (const unsigned short*)stg[buf];
        uint32_t* pb = pB[buf];
        const int kb = chunk * 32;
        #pragma unroll
        for (int i = 0; i < 4; i++) {
            int p = tid + i * 256;              // pair id 0..1023
            int kp = p >> 6, u = p & 63;
            int wn = u >> 4, nth = (u >> 3) & 1, gg = u & 7;
            int n = wn * 32 + nth * 16 + gg;    // entries n and n+8
            int nsp = (n >> 6) * 68 + (n & 63); // staged-tile index part
            int k0 = kb + 2 * kp;
            int o0 = offt[k0], o1 = offt[k0 + 1];
            uint32_t e0 = prmt5410((uint32_t)stp[o0 + nsp], (uint32_t)stp[o1 + nsp]);
            uint32_t e1 = prmt5410((uint32_t)stp[o0 + nsp + 8], (uint32_t)stp[o1 + nsp + 8]);
            *(uint2*)&pb[kp * PBS + wn * 32 + gg * 4 + nth * 2] = make_uint2(e0, e1);
        }
    };

    // ---- 32 HMMA.k16: A direct LDG.128, B dense LDS.128 ----
    auto domma = [&](int chunk, int buf) {
        const uint32_t* pb = pB[buf];
        const uint4* Ag = (const uint4*)((const char*)g_A + (size_t)(chunk * 2 + dblk) * 8192);
        #pragma unroll
        for (int ks2 = 0; ks2 < 2; ks2++) {
            uint4 af[4];
            #pragma unroll
            for (int mt = 0; mt < 4; mt++)
                af[mt] = Ag[((ks2 * 2 + warp_m) * 4 + mt) * 32 + lid];
            uint4 b0 = *(const uint4*)&pb[(ks2 * 8 + tig) * PBS + warp_n * 32 + g * 4];
            uint4 b1 = *(const uint4*)&pb[(ks2 * 8 + tig + 4) * PBS + warp_n * 32 + g * 4];
            uint32_t bf0[4] = {b0.x, b0.y, b0.z, b0.w};
            uint32_t bf1[4] = {b1.x, b1.y, b1.z, b1.w};
            #pragma unroll
            for (int mt = 0; mt < 4; mt++)
                #pragma unroll
                for (int nt = 0; nt < 4; nt++)
                    asm volatile(
                        "mma.sync.aligned.m16n8k16.row.col.f32.f16.f16.f32 "
                        "{%0,%1,%2,%3}, {%4,%5,%6,%7}, {%8,%9}, {%0,%1,%2,%3};"
                        : "+f"(acc[mt][nt][0]), "+f"(acc[mt][nt][1]),
                          "+f"(acc[mt][nt][2]), "+f"(acc[mt][nt][3])
                        : "r"(af[mt].x), "r"(af[mt].y), "r"(af[mt].z), "r"(af[mt].w),
                          "r"(bf0[nt]), "r"(bf1[nt]));
        }
    };

    // ---- pipelined main loop ----
    ldst(0);
    stst(0);
    __syncthreads();
    for (int chunk = 0; chunk < NCH; ++chunk) {
        const int buf = chunk & 1;
        if (chunk + 1 < NCH) ldst(chunk + 1);   // LDG latency hides under build+mma
        build(chunk, buf);
        __syncthreads();                         // pB[buf] visible
        domma(chunk, buf);
        if (chunk + 1 < NCH) stst(buf ^ 1);
        __syncthreads();                         // stg[buf^1] ready; pB reads done
    }

    // ---- epilogue (C frag layout unchanged) ----
    const float b = __ldg(bias);
    #pragma unroll
    for (int mt = 0; mt < 4; mt++) {
        int d = dblk * 128 + warp_m * 64 + mt * 16 + g;
        #pragma unroll
        for (int nt = 0; nt < 4; nt++) {
            int px = warp_n * 32 + nt * 8 + tig * 2;
            int oy = y0 + (px >> 6);
            int ox = px & 63;
            float* o0 = out + (((size_t)img * Dd + d) * Hh + oy) * Ww + ox;
            float* o1 = out + (((size_t)img * Dd + d + 8) * Hh + oy) * Ww + ox;
            *(float2*)o0 = make_float2(acc[mt][nt][0] + b, acc[mt][nt][1] + b);
            *(float2*)o1 = make_float2(acc[mt][nt][2] + b, acc[mt][nt][3] + b);
        }
    }
}

// ---------------------------------------------------------------------------
extern "C" void kernel_launch(void* const* d_in, const int* in_sizes, int n_in,
                              void* d_out, int out_size) {
    const float* x     = (const float*)d_in[0];
    const float* core0 = (const float*)d_in[1];
    const float* core1 = (const float*)d_in[2];
    const float* core2 = (const float*)d_in[3];
    const float* bias  = (const float*)d_in[4];
    float* out = (float*)d_out;

    build_A_kernel<<<Dd, Cc>>>(core0, core1, core2);

    dim3 grid(2, 32, 32);   // dblk, row-pairs, imgs
    conv_main<<<grid, 256>>>(x, bias, out);
}

// round 11
// speedup vs baseline: 1.1647x; 1.1647x over previous
#include <cuda_runtime.h>
#include <cuda_fp16.h>
#include <cstdint>

#define Hh 64
#define Ww 64
#define Cc 128
#define Dd 256
#define KTOT 1152
#define NCH 18              // K chunks of 64
#define STG_SZ 2176         // staged x tile: 8 ch x 4 rows x 68 cols (halves)

// Pre-permuted fp16 weights in m16n8k16 fragment order:
// u32 index: [chunk][dblk][ks2(4)][warp_m(2)][mt(4)][lane(32)][slot(4)], half = +par
__device__ __half g_A[NCH * 2 * 8192];

static __device__ __forceinline__ uint32_t smem_u32(const void* p) {
    uint32_t a;
    asm("{ .reg .u64 t; cvta.to.shared.u64 t, %1; cvt.u32.u64 %0, t; }" : "=r"(a) : "l"(p));
    return a;
}
static __device__ __forceinline__ void cp16(uint32_t saddr, const void* g) {
    asm volatile("cp.async.ca.shared.global [%0], [%1], 16;" :: "r"(saddr), "l"(g));
}
static __device__ __forceinline__ uint32_t prmt5410(uint32_t lo, uint32_t hi) {
    uint32_t r;
    asm("prmt.b32 %0, %1, %2, 0x5410;" : "=r"(r) : "r"(lo), "r"(hi));
    return r;
}

// ---------------------------------------------------------------------------
// Build A in m16n8k16 fragment order. W[d][k], k = c*9 + kh*3 + kw.
// ---------------------------------------------------------------------------
__global__ void build_A_kernel(const float* __restrict__ c0,
                               const float* __restrict__ c1,
                               const float* __restrict__ c2) {
    int d = blockIdx.x, t = threadIdx.x;
    __shared__ float sA[72];
    if (t < 72) {
        int r = t / 9, k = t % 9, kh = k / 3, kw = k % 3;
        float a = 0.f;
        #pragma unroll
        for (int s = 0; s < 4; s++)
            a += c1[d * 96 + r * 12 + kh * 4 + s] * c2[d * 12 + s * 3 + kw];
        sA[t] = a;
    }
    __syncthreads();
    int c = t;
    float cr[8];
    #pragma unroll
    for (int r = 0; r < 8; r++) cr[r] = c0[d * 1024 + c * 8 + r];

    const int dblk = d >> 7, ml = d & 127;
    const int mhalf = ml >> 6, mt = (ml >> 4) & 3, mm = ml & 15;
    const int g = mm & 7, hi = mm >> 3;

    #pragma unroll
    for (int tap = 0; tap < 9; tap++) {
        float w = 0.f;
        #pragma unroll
        for (int r = 0; r < 8; r++) w += cr[r] * sA[r * 9 + tap];
        int k = c * 9 + tap;
        int chunk = k >> 6, kr = k & 63;
        int ks2 = kr >> 4, kk = kr & 15;
        int tig = (kk >> 1) & 3, par = kk & 1, khi = kk >> 3;
        int lane = g * 4 + tig, slot = khi * 2 + hi;
        size_t u32i = (size_t)(chunk * 2 + dblk) * 4096 +
                      (((ks2 * 2 + mhalf) * 4 + mt) * 128 + lane * 4 + slot);
        g_A[u32i * 2 + par] = __float2half_rn(w);
    }
}

// ---------------------------------------------------------------------------
// Main: im2col GEMM-conv, mma.sync m16n8k16 f16 (f32 acc). K-chunk 64.
// Grid (2 dblk, 32 row-pairs, 32 imgs). 256 thr = 8 warps (2 M x 4 N).
// ---------------------------------------------------------------------------
__global__ void __launch_bounds__(256, 2)
conv_main(const float* __restrict__ x, const float* __restrict__ bias,
          float* __restrict__ out) {
    __shared__ uint32_t sAbuf[2][4096];         // A fragments (16KB each)
    __shared__ __half stg[2][STG_SZ];           // staged x tile (fp16)
    __shared__ unsigned short offt[KTOT];       // im2col offset table

    const int tid = threadIdx.x;
    const int wid = tid >> 5, lid = tid & 31;
    const int g = lid >> 2, tig = lid & 3;
    const int warp_m = wid & 1, warp_n = wid >> 1;
    const int dblk = blockIdx.x;
    const int y0 = blockIdx.y * 2;
    const int img = blockIdx.z;
    const float* xim = x + (size_t)img * Cc * Hh * Ww;

    // ---- build offset table (once) ----
    for (int k = tid; k < KTOT; k += 256) {
        int chunk = k >> 6;
        int c = k / 9, tap = k - c * 9;
        int c_lo = (chunk * 64) / 9;
        int kh = tap / 3, kw = tap - kh * 3;
        offt[k] = (unsigned short)((c - c_lo) * 272 + kh * 68 + kw);
    }

    // ---- chunk-invariant staging addresses (validity folded into offset) ----
    int off9[9];
    #pragma unroll
    for (int i = 0; i < 9; i++) {
        int e = tid + i * 256;
        int v = -1;
        if (e < STG_SZ) {
            int cc = e / 272, rem = e - cc * 272;
            int rr = rem / 68, col = rem - rr * 68;
            int gy = y0 - 1 + rr, gx = col - 1;
            if ((unsigned)gy < Hh && (unsigned)gx < Ww)
                v = (cc << 12) + (gy << 6) + gx;
        }
        off9[i] = v;
    }

    float acc[4][4][4];
    #pragma unroll
    for (int mt = 0; mt < 4; mt++)
        #pragma unroll
        for (int nt = 0; nt < 4; nt++)
            #pragma unroll
            for (int i = 0; i < 4; i++) acc[mt][nt][i] = 0.f;

    __half st[9];

    // ---- x-tile LDGs for `chunk` into regs ----
    auto ldst = [&](int chunk) {
        int c_lo = (chunk * 64) / 9;
        const float* base = xim + ((size_t)c_lo << 12);
        unsigned lim = (unsigned)((Cc - c_lo) << 12);
        #pragma unroll
        for (int i = 0; i < 9; i++) {
            float v = 0.f;
            if ((unsigned)off9[i] < lim) v = base[off9[i]];
            st[i] = __float2half_rn(v);
        }
    };
    auto stst = [&](int buf) {
        #pragma unroll
        for (int i = 0; i < 9; i++) {
            int e = tid + i * 256;
            if (e < STG_SZ) stg[buf][e] = st[i];
        }
    };
    auto cpA = [&](int chunk, int buf) {
        const char* gsrc = (const char*)(g_A) + (size_t)(chunk * 2 + dblk) * 16384 + tid * 64;
        uint32_t sdst = smem_u32(&sAbuf[buf][0]) + tid * 64;
        #pragma unroll
        for (int i = 0; i < 4; i++)
            cp16(sdst + i * 16, gsrc + i * 16);
        asm volatile("cp.async.commit_group;" ::: "memory");
    };

    // ---- 64 HMMA.k16 on buffer ----
    auto domma = [&](int chunk, int buf) {
        const unsigned short* stp = (const unsigned short*)stg[buf];
        const int kb = chunk * 64;
        #pragma unroll
        for (int ks2 = 0; ks2 < 4; ks2++) {
            uint4 af[4];
            #pragma unroll
            for (int mt = 0; mt < 4; mt++)
                af[mt] = *(const uint4*)&sAbuf[buf][((ks2 * 2 + warp_m) * 4 + mt) * 128 + lid * 4];
            const int k00 = kb + ks2 * 16 + 2 * tig;
            const int o0l = offt[k00],     o0h = offt[k00 + 1];
            const int o1l = offt[k00 + 8], o1h = offt[k00 + 9];
            uint32_t bf[4][2];
            #pragma unroll
            for (int nt = 0; nt < 4; nt++) {
                int n = warp_n * 32 + nt * 8 + g;
                int nsp = (n >> 6) * 68 + (n & 63);
                bf[nt][0] = prmt5410((uint32_t)stp[o0l + nsp], (uint32_t)stp[o0h + nsp]);
                bf[nt][1] = prmt5410((uint32_t)stp[o1l + nsp], (uint32_t)stp[o1h + nsp]);
            }
            #pragma unroll
            for (int mt = 0; mt < 4; mt++)
                #pragma unroll
                for (int nt = 0; nt < 4; nt++)
                    asm volatile(
                        "mma.sync.aligned.m16n8k16.row.col.f32.f16.f16.f32 "
                        "{%0,%1,%2,%3}, {%4,%5,%6,%7}, {%8,%9}, {%0,%1,%2,%3};"
                        : "+f"(acc[mt][nt][0]), "+f"(acc[mt][nt][1]),
                          "+f"(acc[mt][nt][2]), "+f"(acc[mt][nt][3])
                        : "r"(af[mt].x), "r"(af[mt].y), "r"(af[mt].z), "r"(af[mt].w),
                          "r"(bf[nt][0]), "r"(bf[nt][1]));
        }
    };

    // ---- pipelined main loop (one sync per chunk) ----
    cpA(0, 0);
    ldst(0);
    stst(0);
    asm volatile("cp.async.wait_group 0;" ::: "memory");
    __syncthreads();
    for (int chunk = 0; chunk < NCH; ++chunk) {
        const int buf = chunk & 1;
        if (chunk + 1 < NCH) {
            cpA(chunk + 1, buf ^ 1);
            ldst(chunk + 1);              // LDG latency hides under mma
        }
        domma(chunk, buf);
        if (chunk + 1 < NCH) {
            stst(buf ^ 1);
            asm volatile("cp.async.wait_group 0;" ::: "memory");
        }
        __syncthreads();
    }

    // ---- epilogue (C frag layout unchanged) ----
    const float b = __ldg(bias);
    #pragma unroll
    for (int mt = 0; mt < 4; mt++) {
        int d = dblk * 128 + warp_m * 64 + mt * 16 + g;
        #pragma unroll
        for (int nt = 0; nt < 4; nt++) {
            int px = warp_n * 32 + nt * 8 + tig * 2;
            int oy = y0 + (px >> 6);
            int ox = px & 63;
            float* o0 = out + (((size_t)img * Dd + d) * Hh + oy) * Ww + ox;
            float* o1 = out + (((size_t)img * Dd + d + 8) * Hh + oy) * Ww + ox;
            *(float2*)o0 = make_float2(acc[mt][nt][0] + b, acc[mt][nt][1] + b);
            *(float2*)o1 = make_float2(acc[mt][nt][2] + b, acc[mt][nt][3] + b);
        }
    }
}

// ---------------------------------------------------------------------------
extern "C" void kernel_launch(void* const* d_in, const int* in_sizes, int n_in,
                              void* d_out, int out_size) {
    const float* x     = (const float*)d_in[0];
    const float* core0 = (const float*)d_in[1];
    const float* core1 = (const float*)d_in[2];
    const float* core2 = (const float*)d_in[3];
    const float* bias  = (const float*)d_in[4];
    float* out = (float*)d_out;

    build_A_kernel<<<Dd, Cc>>>(core0, core1, core2);

    dim3 grid(2, 32, 32);   // dblk, row-pairs, imgs
    conv_main<<<grid, 256>>>(x, bias, out);
}